// round 11
// baseline (speedup 1.0000x reference)
#include <cuda_runtime.h>
#include <cuda_bf16.h>
#include <cstddef>

#define NB    4
#define TT_   64
#define LL    64
#define QCH   256
#define KVCH  64
#define GRP   4
#define PPG   16
#define PTOT  (NB*LL*LL)          // 16384 pixels
#define SCALE 0.25f               // 1/sqrt(PPG)

typedef unsigned long long ull;

// Scratch (device globals; no allocation allowed)
__device__ float g_qk[PTOT * 256];   // qk[p][g*64+e], scale folded in
__device__ float g_w [PTOT * 256];   // w [p][g*64+e]

// ---------- packed fp32x2 helpers ----------
__device__ __forceinline__ ull pack2(float lo, float hi) {
    ull r; asm("mov.b64 %0, {%1,%2};" : "=l"(r) : "f"(lo), "f"(hi)); return r;
}
__device__ __forceinline__ void ffma2(ull& d, ull a, ull b) {
    asm("fma.rn.f32x2 %0, %1, %2, %0;" : "+l"(d) : "l"(a), "l"(b));
}
__device__ __forceinline__ void fadd2(ull& d, ull a) {
    asm("add.rn.f32x2 %0, %0, %1;" : "+l"(d) : "l"(a));
}
__device__ __forceinline__ float2 unpack2(ull v) {
    float lo, hi; asm("mov.b64 {%0,%1}, %2;" : "=f"(lo), "=f"(hi) : "l"(v));
    float2 f; f.x = lo; f.y = hi; return f;
}

// Free reinterpret: a loaded float4's register quad IS two packed f32x2 values.
// All uses below are on 16B-aligned addresses (index ≡ 0 mod 4).
union F4U { float4 f; ull u[2]; };

// =====================================================================
// Kernel 1: qk[p][g*64+e] = SCALE * sum_c (q[p]@Wq)[g*16+c] * Wk[e][g*16+c]
// 256 blocks x 512 threads, 64 rows per block. smem 49.6KB -> 2 CTAs/SM,
// 32 warps/SM (fixes wave-starvation: grid can't exceed ~1.7 CTAs/SM).
// =====================================================================
__global__ void __launch_bounds__(512, 2) qk_kernel(const float* __restrict__ q,
                                                    const float* __restrict__ Wq,
                                                    const float* __restrict__ Wk) {
    extern __shared__ float sm[];
    float* sWq = sm;                  // [64][64] chunk of Wq rows (later: sQh)
    float* sQ  = sm + 4096;           // [64][64] chunk of q cols
    float* sWk = sm + 8192;           // [64][66] padded (stride 66)
    float* sQh = sm;                  // aliases sWq after chunk loop
    const int tid = threadIdx.x;
    const int rowBase = blockIdx.x * 64;

    // Load Wk once, padded rows (conflict-free phase-2 reads)
    for (int i = tid; i < 2048; i += 512) {
        const int e = i >> 5, cp = i & 31;
        *(float2*)&sWk[e * 66 + cp * 2] = ((const float2*)Wk)[i];
    }

    const int tr = (tid >> 4) * 2;    // 32 row-groups x 2 rows
    const int tc = (tid & 15) * 4;    // 16 col-groups x 4 cols

    ull acc[2][2];
    acc[0][0] = acc[0][1] = acc[1][0] = acc[1][1] = 0ULL;

    for (int c = 0; c < 4; c++) {
        __syncthreads();   // previous chunk consumed (also orders sWk init)
        {
            const float4* src = (const float4*)(Wq + c * 4096);
            for (int i = tid; i < 1024; i += 512) ((float4*)sWq)[i] = src[i];
        }
        for (int i = tid; i < 1024; i += 512) {
            const int row = i >> 4, c4 = i & 15;
            ((float4*)sQ)[row * 16 + c4] =
                *(const float4*)(q + (size_t)(rowBase + row) * 256 + c * 64 + c4 * 4);
        }
        __syncthreads();

        for (int r = 0; r < 64; r += 4) {
            F4U wp[4];
#pragma unroll
            for (int kk = 0; kk < 4; kk++)
                wp[kk].f = *(const float4*)&sWq[(r + kk) * 64 + tc];
#pragma unroll
            for (int ri = 0; ri < 2; ri++) {
                float4 qv = *(const float4*)&sQ[(tr + ri) * 64 + r];
                ull q0 = pack2(qv.x, qv.x), q1 = pack2(qv.y, qv.y);
                ull q2 = pack2(qv.z, qv.z), q3 = pack2(qv.w, qv.w);
                ffma2(acc[ri][0], q0, wp[0].u[0]); ffma2(acc[ri][1], q0, wp[0].u[1]);
                ffma2(acc[ri][0], q1, wp[1].u[0]); ffma2(acc[ri][1], q1, wp[1].u[1]);
                ffma2(acc[ri][0], q2, wp[2].u[0]); ffma2(acc[ri][1], q2, wp[2].u[1]);
                ffma2(acc[ri][0], q3, wp[3].u[0]); ffma2(acc[ri][1], q3, wp[3].u[1]);
            }
        }
    }

    __syncthreads();   // all reads of sWq done before aliasing as sQh
#pragma unroll
    for (int ri = 0; ri < 2; ri++) {
        float2 a = unpack2(acc[ri][0]);
        float2 b = unpack2(acc[ri][1]);
        float4 o; o.x = a.x; o.y = a.y; o.z = b.x; o.w = b.y;
        *(float4*)&sQh[(tr + ri) * 64 + tc] = o;
    }
    __syncthreads();

    // Phase 2: qk[row][g*64+e]; 2 groups per pass (32 wk regs)
    {
        const int e  = tid & 63;
        const int rq = tid >> 6;   // 0..7, 8 rows each
#pragma unroll
        for (int gp = 0; gp < 2; gp++) {
            ull wk[2][8];
#pragma unroll
            for (int gg = 0; gg < 2; gg++)
#pragma unroll
                for (int c2 = 0; c2 < 8; c2++)
                    wk[gg][c2] = *(const ull*)&sWk[e * 66 + (gp * 2 + gg) * 16 + c2 * 2];
            for (int rr = 0; rr < 8; rr++) {
                const int row = rq * 8 + rr;
                const float* qh = &sQh[row * 64];
                float* dst = &g_qk[(size_t)(rowBase + row) * 256 + e];
#pragma unroll
                for (int gg = 0; gg < 2; gg++) {
                    const int g = gp * 2 + gg;
                    ull a = 0ULL;
#pragma unroll
                    for (int c2 = 0; c2 < 8; c2++)
                        ffma2(a, *(const ull*)&qh[g * 16 + c2 * 2], wk[gg][c2]);
                    float2 v = unpack2(a);
                    dst[g * 64] = SCALE * (v.x + v.y);
                }
            }
        }
    }
}

// =====================================================================
// Kernel 2: per-pixel attention over T. One pixel per 128-thread block.
// UNCHANGED from the validated 143.9us version (scores F4U FFMA2,
// no-max softmax, AV from regs + splatted ps).
// =====================================================================
__global__ void __launch_bounds__(128) attn_kernel(const float* __restrict__ kv) {
    __shared__ __align__(16) float kvs[64 * 68];   // pad 68
    __shared__ __align__(16) float qks[256];
    __shared__ __align__(16) ull   ps2[4 * 64];    // (e,e) splatted, unnormalized
    __shared__ __align__(16) float wsp[4][256];
    __shared__ float red[4][2];                     // per-warp exp-sum partials

    const int p   = blockIdx.x;
    const int tid = threadIdx.x;
    const float* base = kv + (size_t)(p >> 12) * (64ull * 4096ull * 64ull)
                           + (size_t)(p & 4095) * 64;

    if (tid < 64)
        ((float4*)qks)[tid] = ((const float4*)(g_qk + (size_t)p * 256))[tid];

    // Coalesced kv load: thread (f4 = tid&15 channel-quad, sl = tid>>4)
    const int f4 = tid & 15;
    const int sl = tid >> 4;
    ull kreg[8][2];
#pragma unroll
    for (int k = 0; k < 8; k++) {
        const int t = sl + k * 8;
        F4U u; u.f = *(const float4*)(base + (size_t)t * 262144 + f4 * 4);
        *(float4*)&kvs[t * 68 + f4 * 4] = u.f;
        kreg[k][0] = u.u[0];
        kreg[k][1] = u.u[1];
    }
    __syncthreads();

    // Scores + unnormalized exp: thread = (t = tid&63, group pair gh = tid>>6)
    const int t  = tid & 63;
    const int gh = tid >> 6;
    {
        const float* krow = &kvs[t * 68];
        const float* qa = &qks[(2 * gh) * 64];
        const float* qb = qa + 64;
        ull aA0 = 0ULL, aA1 = 0ULL, aB0 = 0ULL, aB1 = 0ULL;
#pragma unroll
        for (int i = 0; i < 8; i++) {
            F4U k0, k1, u0, u1, v0, v1;
            k0.f = *(const float4*)&krow[i * 8];
            k1.f = *(const float4*)&krow[i * 8 + 4];
            u0.f = *(const float4*)&qa[i * 8];
            u1.f = *(const float4*)&qa[i * 8 + 4];
            v0.f = *(const float4*)&qb[i * 8];
            v1.f = *(const float4*)&qb[i * 8 + 4];
            ffma2(aA0, k0.u[0], u0.u[0]);
            ffma2(aA1, k0.u[1], u0.u[1]);
            ffma2(aA0, k1.u[0], u1.u[0]);
            ffma2(aA1, k1.u[1], u1.u[1]);
            ffma2(aB0, k0.u[0], v0.u[0]);
            ffma2(aB1, k0.u[1], v0.u[1]);
            ffma2(aB0, k1.u[0], v1.u[0]);
            ffma2(aB1, k1.u[1], v1.u[1]);
        }
        fadd2(aA0, aA1);
        fadd2(aB0, aB1);
        float2 fa = unpack2(aA0);
        float2 fb = unpack2(aB0);
        float e0 = __expf(fa.x + fa.y);
        float e1 = __expf(fb.x + fb.y);

        float q0 = e0, q1 = e1;
#pragma unroll
        for (int o = 16; o > 0; o >>= 1) {
            q0 += __shfl_xor_sync(0xffffffffu, q0, o);
            q1 += __shfl_xor_sync(0xffffffffu, q1, o);
        }
        const int w = tid >> 5;
        if ((tid & 31) == 0) { red[w][0] = q0; red[w][1] = q1; }
        ps2[(2 * gh) * 64 + t]     = pack2(e0, e0);
        ps2[(2 * gh + 1) * 64 + t] = pack2(e1, e1);
    }
    __syncthreads();

    // AV (unnormalized): kv from regs, splatted ps from smem (LDS.64 bcast)
    {
        ull acc[4][2];
#pragma unroll
        for (int g = 0; g < 4; g++) { acc[g][0] = 0ULL; acc[g][1] = 0ULL; }
#pragma unroll
        for (int k = 0; k < 8; k++) {
            const int tt = sl + k * 8;
#pragma unroll
            for (int g = 0; g < 4; g++) {
                ull pp = ps2[g * 64 + tt];
                ffma2(acc[g][0], pp, kreg[k][0]);
                ffma2(acc[g][1], pp, kreg[k][1]);
            }
        }
        // Pair-reduce across sl parity within the warp (lane ^ 16)
#pragma unroll
        for (int g = 0; g < 4; g++) {
#pragma unroll
            for (int h = 0; h < 2; h++) {
                ull o = __shfl_xor_sync(0xffffffffu, acc[g][h], 16);
                fadd2(acc[g][h], o);
            }
        }
        if ((tid & 16) == 0) {
            const int w = tid >> 5;   // slice 0..3
#pragma unroll
            for (int g = 0; g < 4; g++) {
                float2 a = unpack2(acc[g][0]);
                float2 b = unpack2(acc[g][1]);
                float4 o; o.x = a.x; o.y = a.y; o.z = b.x; o.w = b.y;
                *(float4*)&wsp[w][g * 64 + f4 * 4] = o;
            }
        }
    }
    __syncthreads();

    // Reduce 4 slices, normalize by den (from red), store
    {
        const int o = tid * 2;
        const int g = tid >> 5;   // == o>>6
        const float inv = 1.0f /
            (red[2 * (g >> 1)][g & 1] + red[2 * (g >> 1) + 1][g & 1]);
        float sx = 0.f, sy = 0.f;
#pragma unroll
        for (int slc = 0; slc < 4; slc++) {
            float2 v = *(const float2*)&wsp[slc][o];
            sx += v.x; sy += v.y;
        }
        float2 r; r.x = sx * inv; r.y = sy * inv;
        *(float2*)&g_w[(size_t)p * 256 + o] = r;
    }
}

// =====================================================================
// Kernel 3: x[p] = per-group w@Wv ; out[p] = x@Wout + b
// 256 blocks x 512 threads, 64 rows per block. 96KB smem -> 2 CTAs/SM,
// 32 warps/SM (same wave-starvation fix as qk).
// =====================================================================
__global__ void __launch_bounds__(512, 2) out_kernel(const float* __restrict__ Wv,
                                                     const float* __restrict__ Wout,
                                                     const float* __restrict__ bias,
                                                     float* __restrict__ out) {
    extern __shared__ float sm[];
    float* sBig = sm;                 // [64][256]: w tile, then Wout
    float* sWv  = sm + 16384;         // [64][64]
    float* sX   = sm + 16384 + 4096;  // [64][64]
    const int tid = threadIdx.x;
    const int rowBase = blockIdx.x * 64;

    for (int i = tid; i < 1024; i += 512) ((float4*)sWv)[i] = ((const float4*)Wv)[i];
    {
        const float4* src = (const float4*)(g_w + (size_t)rowBase * 256);
        for (int i = tid; i < 4096; i += 512) ((float4*)sBig)[i] = src[i];
    }
    __syncthreads();

    // Phase 1: x[row][k] = sum_e w[row][g*64+e] * Wv[e][k], g = k>>4
    // thread = (32 row-groups x 2 rows, 16 col-groups x 4 cols)
    {
        const int tr = (tid >> 4) * 2;
        const int tc = (tid & 15) * 4;
        const int g  = tc >> 4;
        ull acc[2][2];
        acc[0][0] = acc[0][1] = acc[1][0] = acc[1][1] = 0ULL;
        for (int e = 0; e < 64; e++) {
            F4U wv; wv.f = *(const float4*)&sWv[e * 64 + tc];
#pragma unroll
            for (int ri = 0; ri < 2; ri++) {
                float x = sBig[(tr + ri) * 256 + g * 64 + e];
                ull xx = pack2(x, x);
                ffma2(acc[ri][0], xx, wv.u[0]);
                ffma2(acc[ri][1], xx, wv.u[1]);
            }
        }
#pragma unroll
        for (int ri = 0; ri < 2; ri++) {
            float2 a = unpack2(acc[ri][0]);
            float2 b = unpack2(acc[ri][1]);
            float4 o; o.x = a.x; o.y = a.y; o.z = b.x; o.w = b.y;
            *(float4*)&sX[(tr + ri) * 64 + tc] = o;
        }
    }
    __syncthreads();

    // Reload sBig with Wout
    for (int i = tid; i < 4096; i += 512) ((float4*)sBig)[i] = ((const float4*)Wout)[i];
    __syncthreads();

    // Phase 2: out[row][d] = b[d] + sum_k x[row][k]*Wout[k][d]
    // thread = (rg = tid>>6 -> 8 rows, c4 = tid&63 -> 4 cols)
    {
        const int rg = tid >> 6;
        const int c4 = tid & 63;
        ull acc[8][2];
#pragma unroll
        for (int i = 0; i < 8; i++) { acc[i][0] = 0ULL; acc[i][1] = 0ULL; }
        for (int k = 0; k < 64; k++) {
            F4U wd; wd.f = *(const float4*)&sBig[k * 256 + c4 * 4];
            const float* xcol = &sX[rg * 8 * 64 + k];
#pragma unroll
            for (int rr = 0; rr < 8; rr++) {
                float xv = xcol[rr * 64];
                ull xx = pack2(xv, xv);
                ffma2(acc[rr][0], xx, wd.u[0]);
                ffma2(acc[rr][1], xx, wd.u[1]);
            }
        }
        float4 bv = ((const float4*)bias)[c4];
#pragma unroll
        for (int rr = 0; rr < 8; rr++) {
            float2 a = unpack2(acc[rr][0]);
            float2 b = unpack2(acc[rr][1]);
            float4 o;
            o.x = a.x + bv.x; o.y = a.y + bv.y;
            o.z = b.x + bv.z; o.w = b.y + bv.w;
            *(float4*)&out[(size_t)(rowBase + rg * 8 + rr) * 256 + c4 * 4] = o;
        }
    }
}

extern "C" void kernel_launch(void* const* d_in, const int* in_sizes, int n_in,
                              void* d_out, int out_size) {
    const float* q    = (const float*)d_in[0];
    const float* kv   = (const float*)d_in[1];
    const float* Wq   = (const float*)d_in[2];
    const float* Wk   = (const float*)d_in[3];
    const float* Wv   = (const float*)d_in[4];
    const float* Wout = (const float*)d_in[5];
    const float* bias = (const float*)d_in[6];
    float* out = (float*)d_out;

    cudaFuncSetAttribute(qk_kernel,  cudaFuncAttributeMaxDynamicSharedMemorySize, 49664);
    cudaFuncSetAttribute(out_kernel, cudaFuncAttributeMaxDynamicSharedMemorySize, 98304);

    qk_kernel<<<PTOT / 64, 512, 49664>>>(q, Wq, Wk);
    attn_kernel<<<PTOT, 128>>>(kv);
    out_kernel<<<PTOT / 64, 512, 98304>>>(Wv, Wout, bias, out);
}